// round 15
// baseline (speedup 1.0000x reference)
#include <cuda_runtime.h>
#include <math.h>

// Problem constants
#define N_B    2
#define S_LEN  2048
#define T_LEN  2048
#define E_DIM  1024
#define H_NUM  16
#define HD     64
#define M_ROWS (N_B * S_LEN)   // 4096

// Scratch (device globals -> no runtime allocation)
__device__ float g_q [M_ROWS * E_DIM];   // tf32 bit patterns
__device__ float g_k [M_ROWS * E_DIM];   // tf32 bit patterns
__device__ float g_v [M_ROWS * E_DIM];   // tf32 bit patterns
__device__ float g_ao[M_ROWS * E_DIM];   // fp32

// ---------------------------------------------------------------------------
// Helpers
// ---------------------------------------------------------------------------
__device__ __forceinline__ unsigned f2tf32(float f) {
    unsigned u;
    asm("cvt.rna.tf32.f32 %0, %1;" : "=r"(u) : "f"(f));
    return u;
}

__device__ __forceinline__ void mma_tf32(float* c, const unsigned* a, const unsigned* b) {
    asm volatile(
        "mma.sync.aligned.m16n8k8.row.col.f32.tf32.tf32.f32 "
        "{%0,%1,%2,%3}, {%4,%5,%6,%7}, {%8,%9}, {%0,%1,%2,%3};"
        : "+f"(c[0]), "+f"(c[1]), "+f"(c[2]), "+f"(c[3])
        : "r"(a[0]), "r"(a[1]), "r"(a[2]), "r"(a[3]), "r"(b[0]), "r"(b[1]));
}

__device__ __forceinline__ void cp16(void* dst_smem, const void* src_gmem) {
    unsigned d = (unsigned)__cvta_generic_to_shared(dst_smem);
    asm volatile("cp.async.ca.shared.global [%0], [%1], 16;" :: "r"(d), "l"(src_gmem));
}

// ---------------------------------------------------------------------------
// GEMM (tf32 tensor core, exact R9 form — measured best):
// C = (A @ W + bias) * scale. 128x128 CTA tile, BK=32, 256 threads = 8 warps.
// cvt.rna at tile fill; tf32 bits in smem; single-buffered (2 CTAs/SM overlap).
// ---------------------------------------------------------------------------
#define ASTR 36
#define BSTR 136

__device__ __forceinline__
void gemm_body(const float* __restrict__ A, const float* __restrict__ W,
               const float* __restrict__ bias, float* __restrict__ C,
               float scale, int tf32_out, int m0, int n0,
               unsigned* As, unsigned* Bs)
{
    const int tid  = threadIdx.x;
    const int lane = tid & 31;
    const int w    = tid >> 5;
    const int wm   = (w >> 2) * 64;
    const int wn   = (w & 3) * 32;

    float acc[4][4][4];
#pragma unroll
    for (int mi = 0; mi < 4; mi++)
#pragma unroll
        for (int ni = 0; ni < 4; ni++)
#pragma unroll
            for (int c = 0; c < 4; c++) acc[mi][ni][c] = 0.f;

    for (int kt = 0; kt < E_DIM; kt += 32) {
#pragma unroll
        for (int p = 0; p < 4; p++) {
            int f = tid + p * 256;
            int r = f >> 3;
            int c = (f & 7) << 2;
            float4 v = *(const float4*)(A + (size_t)(m0 + r) * E_DIM + kt + c);
            As[r * ASTR + c + 0] = f2tf32(v.x);
            As[r * ASTR + c + 1] = f2tf32(v.y);
            As[r * ASTR + c + 2] = f2tf32(v.z);
            As[r * ASTR + c + 3] = f2tf32(v.w);
        }
#pragma unroll
        for (int p = 0; p < 4; p++) {
            int f = tid + p * 256;
            int r = f >> 5;
            int c = (f & 31) << 2;
            float4 v = *(const float4*)(W + (size_t)(kt + r) * E_DIM + n0 + c);
            Bs[r * BSTR + c + 0] = f2tf32(v.x);
            Bs[r * BSTR + c + 1] = f2tf32(v.y);
            Bs[r * BSTR + c + 2] = f2tf32(v.z);
            Bs[r * BSTR + c + 3] = f2tf32(v.w);
        }
        __syncthreads();

#pragma unroll
        for (int kk = 0; kk < 4; kk++) {
            const int kb = kk * 8;
            unsigned af[4][4];
#pragma unroll
            for (int mi = 0; mi < 4; mi++) {
                int rbase = wm + mi * 16 + (lane >> 2);
                int cbase = kb + (lane & 3);
                af[mi][0] = As[rbase * ASTR + cbase];
                af[mi][1] = As[(rbase + 8) * ASTR + cbase];
                af[mi][2] = As[rbase * ASTR + cbase + 4];
                af[mi][3] = As[(rbase + 8) * ASTR + cbase + 4];
            }
            unsigned bf[4][2];
#pragma unroll
            for (int ni = 0; ni < 4; ni++) {
                int kbase = kb + (lane & 3);
                int nbase = wn + ni * 8 + (lane >> 2);
                bf[ni][0] = Bs[kbase * BSTR + nbase];
                bf[ni][1] = Bs[(kbase + 4) * BSTR + nbase];
            }
#pragma unroll
            for (int mi = 0; mi < 4; mi++)
#pragma unroll
                for (int ni = 0; ni < 4; ni++)
                    mma_tf32(acc[mi][ni], af[mi], bf[ni]);
        }
        __syncthreads();
    }

#pragma unroll
    for (int mi = 0; mi < 4; mi++) {
#pragma unroll
        for (int ni = 0; ni < 4; ni++) {
            int row = m0 + wm + mi * 16 + (lane >> 2);
            int col = n0 + wn + ni * 8 + 2 * (lane & 3);
            float v00 = (acc[mi][ni][0] + bias[col])     * scale;
            float v01 = (acc[mi][ni][1] + bias[col + 1]) * scale;
            float v10 = (acc[mi][ni][2] + bias[col])     * scale;
            float v11 = (acc[mi][ni][3] + bias[col + 1]) * scale;
            float2 o0, o1;
            if (tf32_out) {
                o0.x = __uint_as_float(f2tf32(v00));
                o0.y = __uint_as_float(f2tf32(v01));
                o1.x = __uint_as_float(f2tf32(v10));
                o1.y = __uint_as_float(f2tf32(v11));
            } else {
                o0.x = v00; o0.y = v01; o1.x = v10; o1.y = v11;
            }
            *(float2*)(C + (size_t)row * E_DIM + col)       = o0;
            *(float2*)(C + (size_t)(row + 8) * E_DIM + col) = o1;
        }
    }
}

// Fused QKV projections: blockIdx.z selects operand set.
__global__ __launch_bounds__(256, 2)
void gemm_qkv(const float* __restrict__ query, const float* __restrict__ key,
              const float* __restrict__ value,
              const float* __restrict__ Wq, const float* __restrict__ bq,
              const float* __restrict__ Wk, const float* __restrict__ bk,
              const float* __restrict__ Wv, const float* __restrict__ bv,
              float* __restrict__ q_out, float* __restrict__ k_out,
              float* __restrict__ v_out)
{
    __shared__ unsigned As[128 * ASTR];
    __shared__ unsigned Bs[32 * BSTR];
    const int z = blockIdx.z;
    const float* A = (z == 0) ? query : (z == 1) ? key : value;
    const float* W = (z == 0) ? Wq    : (z == 1) ? Wk  : Wv;
    const float* b = (z == 0) ? bq    : (z == 1) ? bk  : bv;
    float*       C = (z == 0) ? q_out : (z == 1) ? k_out : v_out;
    float scale    = (z == 0) ? 0.125f : 1.0f;   // Q pre-scaled by 1/sqrt(HD)
    gemm_body(A, W, b, C, scale, 1, blockIdx.y * 128, blockIdx.x * 128, As, Bs);
}

// Output projection (fp32 out).
__global__ __launch_bounds__(256, 2)
void gemm_tc(const float* __restrict__ A, const float* __restrict__ W,
             const float* __restrict__ bias, float* __restrict__ C,
             float scale, int tf32_out)
{
    __shared__ unsigned As[128 * ASTR];
    __shared__ unsigned Bs[32 * BSTR];
    gemm_body(A, W, bias, C, scale, tf32_out,
              blockIdx.y * 128, blockIdx.x * 128, As, Bs);
}

// ---------------------------------------------------------------------------
// Flash attention v4: v3 fragment structure + P-via-shuffle (no Ps smem)
// + cp.async double-buffered K/V + 1 barrier per t-tile.
// CTA = 128 threads (4 warps) per (n, h, 128-query block). T tiled by 64.
// Warp w owns q rows 32w..32w+31 (two m16 tiles, b-frags shared across both).
// P transpose (accumulator -> A-fragment) done with quad shuffles:
//   A-word (row qr(+8), col 8kk+qc) lives in lane 4qr+(qc>>1) [+2 for col+4]
//   at accumulator slot parity (qc&1).
// Smem: Qs[128][68] | K double buf 2x[64][68] | V double buf 2x[64][72]
// ---------------------------------------------------------------------------
#define QSTR 68
#define VSTR 72
#define SM_Q   0
#define KBUF_WORDS (64 * QSTR)          // 4352
#define VBUF_WORDS (64 * VSTR)          // 4608
#define SM_K0  (128 * QSTR)             // 8704
#define SM_K1  (SM_K0 + KBUF_WORDS)
#define SM_V0  (SM_K1 + KBUF_WORDS)
#define SM_V1  (SM_V0 + VBUF_WORDS)
#define SM_WORDS (SM_V1 + VBUF_WORDS)   // 26624 words
#define SM_BYTES (SM_WORDS * 4)         // 106496 B

#define NT_TILES (T_LEN / 64)           // 32

__global__ __launch_bounds__(128, 2)
void flash_attn_tc(const unsigned* __restrict__ Q, const unsigned* __restrict__ K,
                   const unsigned* __restrict__ V, float* __restrict__ O)
{
    extern __shared__ unsigned sm[];
    unsigned* Qs = sm + SM_Q;
    unsigned* Kb[2] = { sm + SM_K0, sm + SM_K1 };
    unsigned* Vb[2] = { sm + SM_V0, sm + SM_V1 };

    const int tid   = threadIdx.x;
    const int lane  = tid & 31;
    const int w     = tid >> 5;
    const int qr    = lane >> 2;    // 0..7
    const int qc    = lane & 3;     // 0..3
    const int wbase = w * 32;
    const int src0  = (lane & ~3) | (qc >> 1);   // quad lane holding col qc
    const int src1  = src0 + 2;                  // quad lane holding col qc+4
    const bool odd  = (qc & 1) != 0;

    const int qb = blockIdx.x;      // 0..15
    const int h  = blockIdx.y;
    const int n  = blockIdx.z;

    const unsigned* Qbase = Q + (size_t)(n * S_LEN + qb * 128) * E_DIM + h * HD;
    const unsigned* Kbase = K + (size_t)(n * T_LEN) * E_DIM + h * HD;
    const unsigned* Vbase = V + (size_t)(n * T_LEN) * E_DIM + h * HD;

    // Fill row/col for this thread's K/V cp.async slices
    const int fr = tid >> 4;             // 0..7   base row
    const int fc = (tid & 15) << 2;      // 0..60

    // Issue fill of tile 0 (cp.async), then fill Qs with plain stores.
#pragma unroll
    for (int p = 0; p < 8; p++) {
        int r = fr + p * 8;
        cp16(Kb[0] + r * QSTR + fc, Kbase + (size_t)r * E_DIM + fc);
        cp16(Vb[0] + r * VSTR + fc, Vbase + (size_t)r * E_DIM + fc);
    }
    asm volatile("cp.async.commit_group;");

#pragma unroll
    for (int p = 0; p < 16; p++) {
        int f = tid + p * 128;        // 0..2047
        int r = f >> 4;               // 0..127
        int c = (f & 15) << 2;        // 0..60
        uint4 v = *(const uint4*)(Qbase + (size_t)r * E_DIM + c);
        Qs[r * QSTR + c + 0] = v.x;
        Qs[r * QSTR + c + 1] = v.y;
        Qs[r * QSTR + c + 2] = v.z;
        Qs[r * QSTR + c + 3] = v.w;
    }

    float oacc[2][8][4];
#pragma unroll
    for (int mi = 0; mi < 2; mi++)
#pragma unroll
        for (int nt = 0; nt < 8; nt++)
#pragma unroll
            for (int c = 0; c < 4; c++) oacc[mi][nt][c] = 0.f;
    float mrv[2][2], lrv[2][2];
#pragma unroll
    for (int mi = 0; mi < 2; mi++)
#pragma unroll
        for (int hf = 0; hf < 2; hf++) { mrv[mi][hf] = -1e30f; lrv[mi][hf] = 0.f; }

    for (int it = 0; it < NT_TILES; it++) {
        const unsigned* Ks = Kb[it & 1];
        const unsigned* Vs = Vb[it & 1];

        // Wait for this tile's fill; barrier also orders previous tile's
        // smem reads before the next fill (WAR) and Qs visibility on it=0.
        asm volatile("cp.async.wait_group 0;");
        __syncthreads();

        // Prefetch next tile into the other buffer (overlaps compute below)
        if (it + 1 < NT_TILES) {
            unsigned* Kn = Kb[(it + 1) & 1];
            unsigned* Vn = Vb[(it + 1) & 1];
            const unsigned* Kg = Kbase + (size_t)(it + 1) * 64 * E_DIM;
            const unsigned* Vg = Vbase + (size_t)(it + 1) * 64 * E_DIM;
#pragma unroll
            for (int p = 0; p < 8; p++) {
                int r = fr + p * 8;
                cp16(Kn + r * QSTR + fc, Kg + (size_t)r * E_DIM + fc);
                cp16(Vn + r * VSTR + fc, Vg + (size_t)r * E_DIM + fc);
            }
            asm volatile("cp.async.commit_group;");
        }

        // ---- S = Q K^T ----
        float sacc[2][8][4];
#pragma unroll
        for (int mi = 0; mi < 2; mi++)
#pragma unroll
            for (int nt = 0; nt < 8; nt++)
#pragma unroll
                for (int c = 0; c < 4; c++) sacc[mi][nt][c] = 0.f;

#pragma unroll
        for (int kk = 0; kk < 8; kk++) {
            const int kb = kk * 8;
            unsigned a0[4], a1[4];
            int r0 = (wbase + qr) * QSTR + kb + qc;
            a0[0] = Qs[r0];
            a0[1] = Qs[r0 + 8 * QSTR];
            a0[2] = Qs[r0 + 4];
            a0[3] = Qs[r0 + 8 * QSTR + 4];
            int r1 = r0 + 16 * QSTR;
            a1[0] = Qs[r1];
            a1[1] = Qs[r1 + 8 * QSTR];
            a1[2] = Qs[r1 + 4];
            a1[3] = Qs[r1 + 8 * QSTR + 4];
#pragma unroll
            for (int nt = 0; nt < 8; nt++) {
                unsigned b[2];
                int bi = (nt * 8 + qr) * QSTR + kb + qc;
                b[0] = Ks[bi];
                b[1] = Ks[bi + 4];
                mma_tf32(sacc[0][nt], a0, b);
                mma_tf32(sacc[1][nt], a1, b);
            }
        }

        // ---- online softmax (p values stay in sacc registers) ----
#pragma unroll
        for (int mi = 0; mi < 2; mi++) {
#pragma unroll
            for (int hf = 0; hf < 2; hf++) {
                float mx = -1e30f;
#pragma unroll
                for (int nt = 0; nt < 8; nt++)
                    mx = fmaxf(mx, fmaxf(sacc[mi][nt][2 * hf], sacc[mi][nt][2 * hf + 1]));
                mx = fmaxf(mx, __shfl_xor_sync(0xffffffffu, mx, 1));
                mx = fmaxf(mx, __shfl_xor_sync(0xffffffffu, mx, 2));
                float mn = fmaxf(mrv[mi][hf], mx);
                float al = __expf(mrv[mi][hf] - mn);
                mrv[mi][hf] = mn;
                float ls = 0.f;
#pragma unroll
                for (int nt = 0; nt < 8; nt++) {
                    float p0 = __expf(sacc[mi][nt][2 * hf]     - mn);
                    float p1 = __expf(sacc[mi][nt][2 * hf + 1] - mn);
                    sacc[mi][nt][2 * hf]     = p0;
                    sacc[mi][nt][2 * hf + 1] = p1;
                    ls += p0 + p1;
                    oacc[mi][nt][2 * hf]     *= al;
                    oacc[mi][nt][2 * hf + 1] *= al;
                }
                ls += __shfl_xor_sync(0xffffffffu, ls, 1);
                ls += __shfl_xor_sync(0xffffffffu, ls, 2);
                lrv[mi][hf] = lrv[mi][hf] * al + ls;
            }
        }

        // ---- O += P V (P A-fragments via quad shuffles, no smem) ----
#pragma unroll
        for (int kk = 0; kk < 8; kk++) {
            const int kb = kk * 8;
            unsigned a0[4], a1[4];
#pragma unroll
            for (int mi = 0; mi < 2; mi++) {
                float e0 = sacc[mi][kk][0];
                float e1 = sacc[mi][kk][1];
                float e2 = sacc[mi][kk][2];
                float e3 = sacc[mi][kk][3];
                float v00 = __shfl_sync(0xffffffffu, e0, src0);
                float v01 = __shfl_sync(0xffffffffu, e1, src0);
                float v02 = __shfl_sync(0xffffffffu, e2, src0);
                float v03 = __shfl_sync(0xffffffffu, e3, src0);
                float v10 = __shfl_sync(0xffffffffu, e0, src1);
                float v11 = __shfl_sync(0xffffffffu, e1, src1);
                float v12 = __shfl_sync(0xffffffffu, e2, src1);
                float v13 = __shfl_sync(0xffffffffu, e3, src1);
                unsigned* a = (mi == 0) ? a0 : a1;
                a[0] = f2tf32(odd ? v01 : v00);
                a[1] = f2tf32(odd ? v03 : v02);
                a[2] = f2tf32(odd ? v11 : v10);
                a[3] = f2tf32(odd ? v13 : v12);
            }
#pragma unroll
            for (int nt = 0; nt < 8; nt++) {
                unsigned b[2];
                int bi = (kb + qc) * VSTR + nt * 8 + qr;
                b[0] = Vs[bi];
                b[1] = Vs[bi + 4 * VSTR];
                mma_tf32(oacc[0][nt], a0, b);
                mma_tf32(oacc[1][nt], a1, b);
            }
        }
        // no trailing barrier: next iteration's barrier covers the WAR on
        // this tile's K/V buffers (refilled only after that barrier).
    }

    // Normalize and write out: O[n*S + qb*128 + row][h*64 + col]
#pragma unroll
    for (int mi = 0; mi < 2; mi++) {
        float inv0 = 1.f / lrv[mi][0];
        float inv1 = 1.f / lrv[mi][1];
        int grow0 = n * S_LEN + qb * 128 + wbase + mi * 16 + qr;
        int gcol  = h * HD + 2 * qc;
#pragma unroll
        for (int nt = 0; nt < 8; nt++) {
            float2 o0, o1;
            o0.x = oacc[mi][nt][0] * inv0;
            o0.y = oacc[mi][nt][1] * inv0;
            o1.x = oacc[mi][nt][2] * inv1;
            o1.y = oacc[mi][nt][3] * inv1;
            *(float2*)(O + (size_t)grow0 * E_DIM + gcol + nt * 8)       = o0;
            *(float2*)(O + (size_t)(grow0 + 8) * E_DIM + gcol + nt * 8) = o1;
        }
    }
}

// ---------------------------------------------------------------------------
// Launch
// ---------------------------------------------------------------------------
extern "C" void kernel_launch(void* const* d_in, const int* in_sizes, int n_in,
                              void* d_out, int out_size)
{
    const float* query = (const float*)d_in[0];
    const float* key   = (const float*)d_in[1];
    const float* value = (const float*)d_in[2];
    const float* Wq    = (const float*)d_in[3];
    const float* bq    = (const float*)d_in[4];
    const float* Wk    = (const float*)d_in[5];
    const float* bk    = (const float*)d_in[6];
    const float* Wv    = (const float*)d_in[7];
    const float* bv    = (const float*)d_in[8];
    const float* Wo    = (const float*)d_in[9];
    const float* bo    = (const float*)d_in[10];
    float* out = (float*)d_out;

    float *q_p, *k_p, *v_p, *ao_p;
    cudaGetSymbolAddress((void**)&q_p,  g_q);
    cudaGetSymbolAddress((void**)&k_p,  g_k);
    cudaGetSymbolAddress((void**)&v_p,  g_v);
    cudaGetSymbolAddress((void**)&ao_p, g_ao);

    static int configured = 0;
    if (!configured) {
        cudaFuncSetAttribute(flash_attn_tc,
                             cudaFuncAttributeMaxDynamicSharedMemorySize, SM_BYTES);
        cudaFuncSetAttribute(flash_attn_tc,
                             cudaFuncAttributePreferredSharedMemoryCarveout, 100);
        configured = 1;
    }

    // Fused QKV projections (z = 0,1,2), R9 GEMM
    dim3 qkv_grid(E_DIM / 128, M_ROWS / 128, 3);   // 8 x 32 x 3
    gemm_qkv<<<qkv_grid, 256>>>(query, key, value,
                                Wq, bq, Wk, bk, Wv, bv,
                                q_p, k_p, v_p);

    // Flash attention v4 (q-tile 128, double-buffered K/V, shuffle-P)
    dim3 attn_grid(S_LEN / 128, H_NUM, N_B);       // 16 x 16 x 2
    flash_attn_tc<<<attn_grid, 128, SM_BYTES>>>(
        (const unsigned*)q_p, (const unsigned*)k_p, (const unsigned*)v_p, ao_p);

    // Output projection (R9 GEMM)
    dim3 gemm_grid(E_DIM / 128, M_ROWS / 128);     // 8 x 32
    gemm_tc<<<gemm_grid, 256>>>(ao_p, Wo, bo, out, 1.0f, 0);
}